// round 3
// baseline (speedup 1.0000x reference)
#include <cuda_runtime.h>
#include <cstdint>

#define BATCH 2
#define SEQ   2048
#define DIM   2048
#define NH    16
#define NKV   4
#define HD    128
#define QDIM  (NH*HD)      // 2048
#define KVDIM (2*NKV*HD)   // 1024
#define ROWS  (BATCH*SEQ)  // 4096

// Scratch (allocation-free rule: __device__ globals)
__device__ float g_q  [(size_t)ROWS*QDIM];
__device__ float g_kv [(size_t)ROWS*KVDIM];
__device__ float g_vo [(size_t)ROWS*QDIM];
__device__ float g_wqt [(size_t)DIM*QDIM];    // Wq^T  [N,K]
__device__ float g_wkvt[(size_t)DIM*KVDIM];   // Wkv^T [N,K]
__device__ float g_wot [(size_t)QDIM*DIM];    // Wo^T  [N,K]

__device__ __forceinline__ uint32_t tf32_rna(float x) {
    uint32_t y;
    asm("cvt.rna.tf32.f32 %0, %1;" : "=r"(y) : "f"(x));
    return y;
}

// ---------------------------------------------------------------------------
// Transpose: W[K,N] -> Wt[N,K]
// ---------------------------------------------------------------------------
__global__ void transpose_kernel(const float* __restrict__ src,
                                 float* __restrict__ dst, int K, int N)
{
    __shared__ float t[32][33];
    int n0 = blockIdx.x * 32, k0 = blockIdx.y * 32;
    int x = threadIdx.x, y = threadIdx.y;     // 32 x 8
#pragma unroll
    for (int i = 0; i < 32; i += 8)
        t[y + i][x] = src[(size_t)(k0 + y + i) * N + n0 + x];
    __syncthreads();
#pragma unroll
    for (int i = 0; i < 32; i += 8)
        dst[(size_t)(n0 + y + i) * K + k0 + x] = t[x][y + i];
}

// ---------------------------------------------------------------------------
// TF32 mma.sync GEMM: C[M,N] = A[M,K] @ Bt[N,K]^T + bias
// 128x128 tile, BK=16, 256 threads (8 warps x 64x32), double-buffered.
// SMEM layout: As[m][k] / Bs[n][k] with row stride 20 words (conflict-free
// for the m16n8k8 fragment access pattern: bank=(20*d+k)%32 hits all 32).
// ---------------------------------------------------------------------------
#define SMS 20

__global__ __launch_bounds__(256) void gemm_tf32(
    const float* __restrict__ A, const float* __restrict__ Bt,
    const float* __restrict__ bias, float* __restrict__ C,
    int M, int N, int K)
{
    __shared__ __align__(16) uint32_t As[2][128*SMS];
    __shared__ __align__(16) uint32_t Bs[2][128*SMS];

    const int tid  = threadIdx.x;
    const int lane = tid & 31, wid = tid >> 5;
    const int warp_m = (wid >> 2) << 6;   // 0 / 64
    const int warp_n = (wid & 3) << 5;    // 0 / 32 / 64 / 96
    const int gr = lane >> 2, tg = lane & 3;
    const size_t brow0 = (size_t)blockIdx.y * 128;
    const size_t bcol0 = (size_t)blockIdx.x * 128;

    const float* Ag = A  + brow0 * K;
    const float* Bg = Bt + bcol0 * K;

    float acc[4][4][4];
#pragma unroll
    for (int i = 0; i < 4; i++)
#pragma unroll
        for (int j = 0; j < 4; j++)
#pragma unroll
            for (int c = 0; c < 4; c++) acc[i][j][c] = 0.f;

    const int r0 = tid >> 2,          kc0 = (tid & 3) << 2;        // f4 slot 0
    const int r1 = (tid + 256) >> 2,  kc1 = kc0;                   // f4 slot 1

    float4 ra0, ra1, rb0, rb1;
    const int nk = K >> 4;

    // fetch tile 0
    {
        ra0 = *(const float4*)(Ag + (size_t)r0 * K + kc0);
        rb0 = *(const float4*)(Bg + (size_t)r0 * K + kc0);
        ra1 = *(const float4*)(Ag + (size_t)r1 * K + kc1);
        rb1 = *(const float4*)(Bg + (size_t)r1 * K + kc1);
    }
    // store tile 0
    {
        uint4 va = { tf32_rna(ra0.x), tf32_rna(ra0.y), tf32_rna(ra0.z), tf32_rna(ra0.w) };
        uint4 vb = { tf32_rna(rb0.x), tf32_rna(rb0.y), tf32_rna(rb0.z), tf32_rna(rb0.w) };
        *(uint4*)&As[0][r0*SMS + kc0] = va;
        *(uint4*)&Bs[0][r0*SMS + kc0] = vb;
        uint4 wa = { tf32_rna(ra1.x), tf32_rna(ra1.y), tf32_rna(ra1.z), tf32_rna(ra1.w) };
        uint4 wb = { tf32_rna(rb1.x), tf32_rna(rb1.y), tf32_rna(rb1.z), tf32_rna(rb1.w) };
        *(uint4*)&As[0][r1*SMS + kc1] = wa;
        *(uint4*)&Bs[0][r1*SMS + kc1] = wb;
    }
    __syncthreads();

    for (int kt = 0; kt < nk; kt++) {
        const int buf = kt & 1;
        if (kt + 1 < nk) {
            const int k0 = (kt + 1) << 4;
            ra0 = *(const float4*)(Ag + (size_t)r0 * K + k0 + kc0);
            rb0 = *(const float4*)(Bg + (size_t)r0 * K + k0 + kc0);
            ra1 = *(const float4*)(Ag + (size_t)r1 * K + k0 + kc1);
            rb1 = *(const float4*)(Bg + (size_t)r1 * K + k0 + kc1);
        }

#pragma unroll
        for (int ks = 0; ks < 2; ks++) {
            const int kb = ks << 3;
            uint32_t af[4][4], bf[4][2];
#pragma unroll
            for (int mt = 0; mt < 4; mt++) {
                const uint32_t* p = &As[buf][(warp_m + mt*16 + gr)*SMS + kb + tg];
                af[mt][0] = p[0];
                af[mt][1] = p[8*SMS];
                af[mt][2] = p[4];
                af[mt][3] = p[8*SMS + 4];
            }
#pragma unroll
            for (int nt = 0; nt < 4; nt++) {
                const uint32_t* p = &Bs[buf][(warp_n + nt*8 + gr)*SMS + kb + tg];
                bf[nt][0] = p[0];
                bf[nt][1] = p[4];
            }
#pragma unroll
            for (int mt = 0; mt < 4; mt++)
#pragma unroll
                for (int nt = 0; nt < 4; nt++) {
                    asm volatile(
                        "mma.sync.aligned.m16n8k8.row.col.f32.tf32.tf32.f32 "
                        "{%0,%1,%2,%3}, {%4,%5,%6,%7}, {%8,%9}, {%0,%1,%2,%3};"
                        : "+f"(acc[mt][nt][0]), "+f"(acc[mt][nt][1]),
                          "+f"(acc[mt][nt][2]), "+f"(acc[mt][nt][3])
                        : "r"(af[mt][0]), "r"(af[mt][1]), "r"(af[mt][2]), "r"(af[mt][3]),
                          "r"(bf[nt][0]), "r"(bf[nt][1]));
                }
        }

        if (kt + 1 < nk) {
            const int nb = buf ^ 1;
            uint4 va = { tf32_rna(ra0.x), tf32_rna(ra0.y), tf32_rna(ra0.z), tf32_rna(ra0.w) };
            uint4 vb = { tf32_rna(rb0.x), tf32_rna(rb0.y), tf32_rna(rb0.z), tf32_rna(rb0.w) };
            *(uint4*)&As[nb][r0*SMS + kc0] = va;
            *(uint4*)&Bs[nb][r0*SMS + kc0] = vb;
            uint4 wa = { tf32_rna(ra1.x), tf32_rna(ra1.y), tf32_rna(ra1.z), tf32_rna(ra1.w) };
            uint4 wb = { tf32_rna(rb1.x), tf32_rna(rb1.y), tf32_rna(rb1.z), tf32_rna(rb1.w) };
            *(uint4*)&As[nb][r1*SMS + kc1] = wa;
            *(uint4*)&Bs[nb][r1*SMS + kc1] = wb;
        }
        __syncthreads();
    }

    // Epilogue: acc -> C with bias (float2 per c0/c1 pair)
#pragma unroll
    for (int mt = 0; mt < 4; mt++) {
#pragma unroll
        for (int nt = 0; nt < 4; nt++) {
            const size_t row = brow0 + warp_m + mt*16 + gr;
            const int    col = (int)bcol0 + warp_n + nt*8 + tg*2;
            const float b0 = bias[col], b1 = bias[col + 1];
            float2 v0 = { acc[mt][nt][0] + b0, acc[mt][nt][1] + b1 };
            float2 v1 = { acc[mt][nt][2] + b0, acc[mt][nt][3] + b1 };
            *(float2*)(C + row * N + col)       = v0;
            *(float2*)(C + (row + 8) * N + col) = v1;
        }
    }
}

// ---------------------------------------------------------------------------
// RoPE applied in-place to Q (16 heads) and K part of KV (4 heads)
// ---------------------------------------------------------------------------
__global__ void rope_kernel(float* __restrict__ q, float* __restrict__ kv,
                            const float* __restrict__ cs, const float* __restrict__ sn)
{
    const int row = blockIdx.x;
    const int s = row & (SEQ-1);
    for (int t = threadIdx.x; t < (NH+NKV)*64; t += blockDim.x) {
        int head = t >> 6, d = t & 63;
        float c  = cs[s*64 + d];
        float si = sn[s*64 + d];
        float* p1;
        if (head < NH) p1 = q  + (size_t)row*QDIM  + head*HD + d;
        else           p1 = kv + (size_t)row*KVDIM + (head-NH)*HD + d;
        float* p2 = p1 + 64;
        float x1 = *p1, x2 = *p2;
        *p1 = x1*c - x2*si;
        *p2 = x1*si + x2*c;
    }
}

// ---------------------------------------------------------------------------
// Flash attention fp32 (unchanged from R0 passing version)
// ---------------------------------------------------------------------------
#define FA_SMEM ((128*64 + 128*64 + 64*128 + 64*65) * 4)

__global__ __launch_bounds__(256) void flash_attn(
    const float* __restrict__ Q, const float* __restrict__ KV,
    float* __restrict__ O, const int* __restrict__ causal_p)
{
    extern __shared__ float sm[];
    float* Qs = sm;
    float* Ks = Qs + 128*64;
    float* Vs = Ks + 128*64;
    float* Ps = Vs + 64*128;

    const int causal = *causal_p;
    const int qt = blockIdx.x, h = blockIdx.y, b = blockIdx.z;
    const int kh = h >> 2;
    const int q0 = qt << 6;
    const int tid = threadIdx.x;
    const int tx = tid & 15, ty = tid >> 4;
    const float scale = 0.08838834764831845f;

    const float* Qb = Q + ((size_t)(b*SEQ + q0))*QDIM + h*HD;
    for (int i = tid; i < 64*32; i += 256) {
        int r = i >> 5, d4 = (i & 31) << 2;
        float4 v = *(const float4*)(Qb + (size_t)r*QDIM + d4);
        Qs[(d4+0)*64 + r] = v.x*scale; Qs[(d4+1)*64 + r] = v.y*scale;
        Qs[(d4+2)*64 + r] = v.z*scale; Qs[(d4+3)*64 + r] = v.w*scale;
    }

    float m[4], l[4], o[4][8];
#pragma unroll
    for (int i = 0; i < 4; i++) {
        m[i] = -1e30f; l[i] = 0.f;
#pragma unroll
        for (int j = 0; j < 8; j++) o[i][j] = 0.f;
    }

    const int nkt = causal ? (qt + 1) : (SEQ >> 6);
    const float* Kb = KV + (size_t)(b*SEQ)*KVDIM + kh*HD;

    for (int kt = 0; kt < nkt; kt++) {
        __syncthreads();
        for (int i = tid; i < 64*32; i += 256) {
            int r = i >> 5, d4 = (i & 31) << 2;
            const float* kp = Kb + (size_t)((kt<<6) + r)*KVDIM + d4;
            float4 k4 = *(const float4*)kp;
            Ks[(d4+0)*64 + r] = k4.x; Ks[(d4+1)*64 + r] = k4.y;
            Ks[(d4+2)*64 + r] = k4.z; Ks[(d4+3)*64 + r] = k4.w;
            float4 v4 = *(const float4*)(kp + NKV*HD);
            *(float4*)&Vs[r*128 + d4] = v4;
        }
        __syncthreads();

        float sacc[4][4];
#pragma unroll
        for (int i = 0; i < 4; i++)
#pragma unroll
            for (int j = 0; j < 4; j++) sacc[i][j] = 0.f;

#pragma unroll 8
        for (int d = 0; d < 128; d++) {
            float af[4], bf[4];
            *(float4*)af = *(const float4*)&Qs[d*64 + ty*4];
            *(float4*)bf = *(const float4*)&Ks[d*64 + tx*4];
#pragma unroll
            for (int i = 0; i < 4; i++)
#pragma unroll
                for (int j = 0; j < 4; j++) sacc[i][j] += af[i]*bf[j];
        }

        const bool diag = (causal && kt == qt);
#pragma unroll
        for (int i = 0; i < 4; i++) {
            const int qg = q0 + ty*4 + i;
            if (diag) {
#pragma unroll
                for (int j = 0; j < 4; j++) {
                    int kg = (kt << 6) + tx*4 + j;
                    if (kg > qg) sacc[i][j] = -1e30f;
                }
            }
            float rm = fmaxf(fmaxf(sacc[i][0], sacc[i][1]),
                             fmaxf(sacc[i][2], sacc[i][3]));
            rm = fmaxf(rm, __shfl_xor_sync(0xffffffffu, rm, 8));
            rm = fmaxf(rm, __shfl_xor_sync(0xffffffffu, rm, 4));
            rm = fmaxf(rm, __shfl_xor_sync(0xffffffffu, rm, 2));
            rm = fmaxf(rm, __shfl_xor_sync(0xffffffffu, rm, 1));
            float mnew   = fmaxf(m[i], rm);
            float factor = __expf(m[i] - mnew);
            float rs = 0.f;
#pragma unroll
            for (int j = 0; j < 4; j++) {
                float p = __expf(sacc[i][j] - mnew);
                Ps[(ty*4+i)*65 + tx*4 + j] = p;
                rs += p;
            }
            rs += __shfl_xor_sync(0xffffffffu, rs, 8);
            rs += __shfl_xor_sync(0xffffffffu, rs, 4);
            rs += __shfl_xor_sync(0xffffffffu, rs, 2);
            rs += __shfl_xor_sync(0xffffffffu, rs, 1);
            l[i] = l[i]*factor + rs;
            m[i] = mnew;
#pragma unroll
            for (int j = 0; j < 8; j++) o[i][j] *= factor;
        }
        __syncthreads();

#pragma unroll 4
        for (int k = 0; k < 64; k++) {
            float vf[8];
            *(float4*)(vf)   = *(const float4*)&Vs[k*128 + tx*8];
            *(float4*)(vf+4) = *(const float4*)&Vs[k*128 + tx*8 + 4];
#pragma unroll
            for (int i = 0; i < 4; i++) {
                float p = Ps[(ty*4+i)*65 + k];
#pragma unroll
                for (int j = 0; j < 8; j++) o[i][j] += p*vf[j];
            }
        }
    }

    float* Ob = O + ((size_t)(b*SEQ + q0))*QDIM + h*HD;
#pragma unroll
    for (int i = 0; i < 4; i++) {
        int r = ty*4 + i;
        float inv = 1.0f / l[i];
        float of[8];
#pragma unroll
        for (int j = 0; j < 8; j++) of[j] = o[i][j]*inv;
        *(float4*)(Ob + (size_t)r*QDIM + tx*8)     = *(float4*)(of);
        *(float4*)(Ob + (size_t)r*QDIM + tx*8 + 4) = *(float4*)(of+4);
    }
}

// ---------------------------------------------------------------------------
extern "C" void kernel_launch(void* const* d_in, const int* in_sizes, int n_in,
                              void* d_out, int out_size)
{
    const float* x    = (const float*)d_in[0];
    const float* cosp = (const float*)d_in[1];
    const float* sinp = (const float*)d_in[2];
    const float* Wq   = (const float*)d_in[3];
    const float* bq   = (const float*)d_in[4];
    const float* Wkv  = (const float*)d_in[5];
    const float* bkv  = (const float*)d_in[6];
    const float* Wo   = (const float*)d_in[7];
    const float* bo   = (const float*)d_in[8];
    const int*   causal = (const int*)d_in[9];
    float* out = (float*)d_out;

    float *q, *kv, *vo, *wqt, *wkvt, *wot;
    cudaGetSymbolAddress((void**)&q,    g_q);
    cudaGetSymbolAddress((void**)&kv,   g_kv);
    cudaGetSymbolAddress((void**)&vo,   g_vo);
    cudaGetSymbolAddress((void**)&wqt,  g_wqt);
    cudaGetSymbolAddress((void**)&wkvt, g_wkvt);
    cudaGetSymbolAddress((void**)&wot,  g_wot);

    cudaFuncSetAttribute(flash_attn,
                         cudaFuncAttributeMaxDynamicSharedMemorySize, FA_SMEM);

    // W transposes: [K,N] -> [N,K]
    transpose_kernel<<<dim3(QDIM/32,  DIM/32),  dim3(32,8)>>>(Wq,  wqt,  DIM,  QDIM);
    transpose_kernel<<<dim3(KVDIM/32, DIM/32),  dim3(32,8)>>>(Wkv, wkvt, DIM,  KVDIM);
    transpose_kernel<<<dim3(DIM/32,   QDIM/32), dim3(32,8)>>>(Wo,  wot,  QDIM, DIM);

    // projections on tensor cores (mma.sync tf32)
    gemm_tf32<<<dim3(QDIM/128,  ROWS/128), 256>>>(x, wqt,  bq,  q,  ROWS, QDIM,  DIM);
    gemm_tf32<<<dim3(KVDIM/128, ROWS/128), 256>>>(x, wkvt, bkv, kv, ROWS, KVDIM, DIM);

    rope_kernel<<<ROWS, 256>>>(q, kv, cosp, sinp);
    flash_attn<<<dim3(SEQ/64, NH, BATCH), 256, FA_SMEM>>>(q, kv, vo, causal);

    gemm_tf32<<<dim3(DIM/128, ROWS/128), 256>>>(vo, wot, bo, out, ROWS, DIM, DIM);
}

// round 4
// speedup vs baseline: 3.6023x; 3.6023x over previous
#include <cuda_runtime.h>
#include <cstdint>

#define BATCH 2
#define SEQ   2048
#define DIM   2048
#define NH    16
#define NKV   4
#define HD    128
#define QDIM  (NH*HD)      // 2048
#define KVDIM (2*NKV*HD)   // 1024
#define ROWS  (BATCH*SEQ)  // 4096

// Scratch (allocation-free rule: __device__ globals)
__device__ float g_q  [(size_t)ROWS*QDIM];
__device__ float g_kv [(size_t)ROWS*KVDIM];
__device__ float g_vo [(size_t)ROWS*QDIM];
__device__ float g_wqt [(size_t)DIM*QDIM];    // Wq^T  [N,K]
__device__ float g_wkvt[(size_t)DIM*KVDIM];   // Wkv^T [N,K]
__device__ float g_wot [(size_t)QDIM*DIM];    // Wo^T  [N,K]

__device__ __forceinline__ uint32_t tf32_rna(float x) {
    uint32_t y;
    asm("cvt.rna.tf32.f32 %0, %1;" : "=r"(y) : "f"(x));
    return y;
}
__device__ __forceinline__ float ex2f(float x) {
    float y;
    asm("ex2.approx.ftz.f32 %0, %1;" : "=f"(y) : "f"(x));
    return y;
}

#define MMA_TF32(c, a, b0, b1)                                                \
    asm volatile("mma.sync.aligned.m16n8k8.row.col.f32.tf32.tf32.f32 "        \
        "{%0,%1,%2,%3},{%4,%5,%6,%7},{%8,%9},{%0,%1,%2,%3};"                  \
        : "+f"((c)[0]), "+f"((c)[1]), "+f"((c)[2]), "+f"((c)[3])              \
        : "r"((a)[0]), "r"((a)[1]), "r"((a)[2]), "r"((a)[3]),                 \
          "r"(b0), "r"(b1))

// ---------------------------------------------------------------------------
// Transpose: W[K,N] -> Wt[N,K]
// ---------------------------------------------------------------------------
__global__ void transpose_kernel(const float* __restrict__ src,
                                 float* __restrict__ dst, int K, int N)
{
    __shared__ float t[32][33];
    int n0 = blockIdx.x * 32, k0 = blockIdx.y * 32;
    int x = threadIdx.x, y = threadIdx.y;     // 32 x 8
#pragma unroll
    for (int i = 0; i < 32; i += 8)
        t[y + i][x] = src[(size_t)(k0 + y + i) * N + n0 + x];
    __syncthreads();
#pragma unroll
    for (int i = 0; i < 32; i += 8)
        dst[(size_t)(n0 + y + i) * K + k0 + x] = t[x][y + i];
}

// ---------------------------------------------------------------------------
// TF32 mma.sync GEMM (as R3-passing, + min 2 CTAs/SM)
// ---------------------------------------------------------------------------
#define SMS 20

__global__ __launch_bounds__(256, 2) void gemm_tf32(
    const float* __restrict__ A, const float* __restrict__ Bt,
    const float* __restrict__ bias, float* __restrict__ C,
    int M, int N, int K)
{
    __shared__ __align__(16) uint32_t As[2][128*SMS];
    __shared__ __align__(16) uint32_t Bs[2][128*SMS];

    const int tid  = threadIdx.x;
    const int lane = tid & 31, wid = tid >> 5;
    const int warp_m = (wid >> 2) << 6;
    const int warp_n = (wid & 3) << 5;
    const int gr = lane >> 2, tg = lane & 3;
    const size_t brow0 = (size_t)blockIdx.y * 128;
    const size_t bcol0 = (size_t)blockIdx.x * 128;

    const float* Ag = A  + brow0 * K;
    const float* Bg = Bt + bcol0 * K;

    float acc[4][4][4];
#pragma unroll
    for (int i = 0; i < 4; i++)
#pragma unroll
        for (int j = 0; j < 4; j++)
#pragma unroll
            for (int c = 0; c < 4; c++) acc[i][j][c] = 0.f;

    const int r0 = tid >> 2,          kc0 = (tid & 3) << 2;
    const int r1 = (tid + 256) >> 2,  kc1 = kc0;

    float4 ra0, ra1, rb0, rb1;
    const int nk = K >> 4;

    ra0 = *(const float4*)(Ag + (size_t)r0 * K + kc0);
    rb0 = *(const float4*)(Bg + (size_t)r0 * K + kc0);
    ra1 = *(const float4*)(Ag + (size_t)r1 * K + kc1);
    rb1 = *(const float4*)(Bg + (size_t)r1 * K + kc1);
    {
        uint4 va = { tf32_rna(ra0.x), tf32_rna(ra0.y), tf32_rna(ra0.z), tf32_rna(ra0.w) };
        uint4 vb = { tf32_rna(rb0.x), tf32_rna(rb0.y), tf32_rna(rb0.z), tf32_rna(rb0.w) };
        *(uint4*)&As[0][r0*SMS + kc0] = va;
        *(uint4*)&Bs[0][r0*SMS + kc0] = vb;
        uint4 wa = { tf32_rna(ra1.x), tf32_rna(ra1.y), tf32_rna(ra1.z), tf32_rna(ra1.w) };
        uint4 wb = { tf32_rna(rb1.x), tf32_rna(rb1.y), tf32_rna(rb1.z), tf32_rna(rb1.w) };
        *(uint4*)&As[0][r1*SMS + kc1] = wa;
        *(uint4*)&Bs[0][r1*SMS + kc1] = wb;
    }
    __syncthreads();

    for (int kt = 0; kt < nk; kt++) {
        const int buf = kt & 1;
        if (kt + 1 < nk) {
            const int k0 = (kt + 1) << 4;
            ra0 = *(const float4*)(Ag + (size_t)r0 * K + k0 + kc0);
            rb0 = *(const float4*)(Bg + (size_t)r0 * K + k0 + kc0);
            ra1 = *(const float4*)(Ag + (size_t)r1 * K + k0 + kc1);
            rb1 = *(const float4*)(Bg + (size_t)r1 * K + k0 + kc1);
        }

#pragma unroll
        for (int ks = 0; ks < 2; ks++) {
            const int kb = ks << 3;
            uint32_t af[4][4], bf[4][2];
#pragma unroll
            for (int mt = 0; mt < 4; mt++) {
                const uint32_t* p = &As[buf][(warp_m + mt*16 + gr)*SMS + kb + tg];
                af[mt][0] = p[0];
                af[mt][1] = p[8*SMS];
                af[mt][2] = p[4];
                af[mt][3] = p[8*SMS + 4];
            }
#pragma unroll
            for (int nt = 0; nt < 4; nt++) {
                const uint32_t* p = &Bs[buf][(warp_n + nt*8 + gr)*SMS + kb + tg];
                bf[nt][0] = p[0];
                bf[nt][1] = p[4];
            }
#pragma unroll
            for (int mt = 0; mt < 4; mt++)
#pragma unroll
                for (int nt = 0; nt < 4; nt++)
                    MMA_TF32(acc[mt][nt], af[mt], bf[nt][0], bf[nt][1]);
        }

        if (kt + 1 < nk) {
            const int nb = buf ^ 1;
            uint4 va = { tf32_rna(ra0.x), tf32_rna(ra0.y), tf32_rna(ra0.z), tf32_rna(ra0.w) };
            uint4 vb = { tf32_rna(rb0.x), tf32_rna(rb0.y), tf32_rna(rb0.z), tf32_rna(rb0.w) };
            *(uint4*)&As[nb][r0*SMS + kc0] = va;
            *(uint4*)&Bs[nb][r0*SMS + kc0] = vb;
            uint4 wa = { tf32_rna(ra1.x), tf32_rna(ra1.y), tf32_rna(ra1.z), tf32_rna(ra1.w) };
            uint4 wb = { tf32_rna(rb1.x), tf32_rna(rb1.y), tf32_rna(rb1.z), tf32_rna(rb1.w) };
            *(uint4*)&As[nb][r1*SMS + kc1] = wa;
            *(uint4*)&Bs[nb][r1*SMS + kc1] = wb;
        }
        __syncthreads();
    }

#pragma unroll
    for (int mt = 0; mt < 4; mt++) {
#pragma unroll
        for (int nt = 0; nt < 4; nt++) {
            const size_t row = brow0 + warp_m + mt*16 + gr;
            const int    col = (int)bcol0 + warp_n + nt*8 + tg*2;
            const float b0 = bias[col], b1 = bias[col + 1];
            float2 v0 = { acc[mt][nt][0] + b0, acc[mt][nt][1] + b1 };
            float2 v1 = { acc[mt][nt][2] + b0, acc[mt][nt][3] + b1 };
            *(float2*)(C + row * N + col)       = v0;
            *(float2*)(C + (row + 8) * N + col) = v1;
        }
    }
}

// ---------------------------------------------------------------------------
// RoPE applied in-place to Q (16 heads) and K part of KV (4 heads)
// ---------------------------------------------------------------------------
__global__ void rope_kernel(float* __restrict__ q, float* __restrict__ kv,
                            const float* __restrict__ cs, const float* __restrict__ sn)
{
    const int row = blockIdx.x;
    const int s = row & (SEQ-1);
    for (int t = threadIdx.x; t < (NH+NKV)*64; t += blockDim.x) {
        int head = t >> 6, d = t & 63;
        float c  = cs[s*64 + d];
        float si = sn[s*64 + d];
        float* p1;
        if (head < NH) p1 = q  + (size_t)row*QDIM  + head*HD + d;
        else           p1 = kv + (size_t)row*KVDIM + (head-NH)*HD + d;
        float* p2 = p1 + 64;
        float x1 = *p1, x2 = *p2;
        *p1 = x1*c - x2*si;
        *p2 = x1*si + x2*c;
    }
}

// ---------------------------------------------------------------------------
// Flash attention, tf32 mma.sync
// CTA = 128 q-rows x 1 head x 1 batch; 8 warps, each warp owns 16 q-rows.
// SMEM: Ks[64][132] + Vs[64][132] (tf32), Ps[8 warps][16][68] (tf32)
// Q tile staged through Ks∪Vs region once, then held in registers as A-frags.
// ---------------------------------------------------------------------------
#define FA_SMEM ((2*64*132 + 8*16*68) * 4)    // 102400 B

__global__ __launch_bounds__(256) void flash_tf32(
    const float* __restrict__ Q, const float* __restrict__ KV,
    float* __restrict__ O, const int* __restrict__ causal_p)
{
    extern __shared__ uint32_t fsm[];
    uint32_t* Ks = fsm;                 // [64][132]
    uint32_t* Vs = fsm + 64*132;        // [64][132]
    uint32_t* Ps = fsm + 2*64*132;      // [8][16][68]

    const int causal = *causal_p;
    const int qt = blockIdx.x, h = blockIdx.y, b = blockIdx.z;
    const int q0 = qt << 7;             // 128 q-rows per CTA
    const int tid = threadIdx.x;
    const int lane = tid & 31, wid = tid >> 5;
    const int gr = lane >> 2, tg = lane & 3;
    const int m0 = wid << 4;            // warp q-row offset in tile
    // softmax scale with log2(e) folded in (we use ex2 for exp)
    const float qscale = 0.08838834764831845f * 1.4426950408889634f;

    // ---- stage Q (128x128) pre-scaled + rna into fsm[128][132], then frags
    const float* Qb = Q + ((size_t)(b*SEQ + q0))*QDIM + h*HD;
    for (int i = tid; i < 128*32; i += 256) {
        int r = i >> 5, c4 = (i & 31) << 2;
        float4 v = *(const float4*)(Qb + (size_t)r*QDIM + c4);
        uint4 u = { tf32_rna(v.x*qscale), tf32_rna(v.y*qscale),
                    tf32_rna(v.z*qscale), tf32_rna(v.w*qscale) };
        *(uint4*)&fsm[r*132 + c4] = u;
    }
    __syncthreads();

    uint32_t aq[16][4];
#pragma unroll
    for (int kb = 0; kb < 16; kb++) {
        const uint32_t* p = &fsm[(m0 + gr)*132 + kb*8 + tg];
        aq[kb][0] = p[0];
        aq[kb][1] = p[8*132];
        aq[kb][2] = p[4];
        aq[kb][3] = p[8*132 + 4];
    }

    float m_[2] = { -1e30f, -1e30f }, l_[2] = { 0.f, 0.f };
    float oacc[16][4];
#pragma unroll
    for (int nt = 0; nt < 16; nt++)
#pragma unroll
        for (int c = 0; c < 4; c++) oacc[nt][c] = 0.f;

    const int full = causal ? (q0 >> 6) : (1 << 30);   // unmasked k-tiles
    const int nkt  = causal ? ((q0 >> 6) + 2) : (SEQ >> 6);
    const float* Kb = KV + (size_t)(b*SEQ)*KVDIM + (h >> 2)*HD;
    uint32_t* Pw = Ps + wid*16*68;

    for (int kt = 0; kt < nkt; kt++) {
        __syncthreads();   // everyone done with fsm (Q frags / prev tile)
        // ---- load K,V (64x128) -> rna tf32 smem
        for (int i = tid; i < 64*32; i += 256) {
            int r = i >> 5, c4 = (i & 31) << 2;
            const float* kp = Kb + (size_t)((kt << 6) + r)*KVDIM + c4;
            float4 k4 = *(const float4*)kp;
            float4 v4 = *(const float4*)(kp + NKV*HD);
            uint4 ku = { tf32_rna(k4.x), tf32_rna(k4.y), tf32_rna(k4.z), tf32_rna(k4.w) };
            uint4 vu = { tf32_rna(v4.x), tf32_rna(v4.y), tf32_rna(v4.z), tf32_rna(v4.w) };
            *(uint4*)&Ks[r*132 + c4] = ku;
            *(uint4*)&Vs[r*132 + c4] = vu;
        }
        __syncthreads();

        // ---- S = Q K^T : 8 n-tiles of 8 keys
        float sacc[8][4];
#pragma unroll
        for (int nt = 0; nt < 8; nt++)
#pragma unroll
            for (int c = 0; c < 4; c++) sacc[nt][c] = 0.f;

#pragma unroll
        for (int kb = 0; kb < 16; kb++) {
            uint32_t bf[8][2];
#pragma unroll
            for (int nt = 0; nt < 8; nt++) {
                const uint32_t* p = &Ks[(nt*8 + gr)*132 + kb*8 + tg];
                bf[nt][0] = p[0];
                bf[nt][1] = p[4];
            }
#pragma unroll
            for (int nt = 0; nt < 8; nt++)
                MMA_TF32(sacc[nt], aq[kb], bf[nt][0], bf[nt][1]);
        }

        // ---- causal mask on diag tiles
        if (causal && kt >= full) {
            const int row0 = q0 + m0 + gr, row1 = row0 + 8;
#pragma unroll
            for (int nt = 0; nt < 8; nt++) {
                int col = (kt << 6) + nt*8 + tg*2;
                if (col     > row0) sacc[nt][0] = -1e30f;
                if (col + 1 > row0) sacc[nt][1] = -1e30f;
                if (col     > row1) sacc[nt][2] = -1e30f;
                if (col + 1 > row1) sacc[nt][3] = -1e30f;
            }
        }

        // ---- online softmax (rows gr and gr+8), P -> smem (tf32)
        float rm0 = -1e30f, rm1 = -1e30f;
#pragma unroll
        for (int nt = 0; nt < 8; nt++) {
            rm0 = fmaxf(rm0, fmaxf(sacc[nt][0], sacc[nt][1]));
            rm1 = fmaxf(rm1, fmaxf(sacc[nt][2], sacc[nt][3]));
        }
        rm0 = fmaxf(rm0, __shfl_xor_sync(0xffffffffu, rm0, 1));
        rm0 = fmaxf(rm0, __shfl_xor_sync(0xffffffffu, rm0, 2));
        rm1 = fmaxf(rm1, __shfl_xor_sync(0xffffffffu, rm1, 1));
        rm1 = fmaxf(rm1, __shfl_xor_sync(0xffffffffu, rm1, 2));

        float mn0 = fmaxf(m_[0], rm0), mn1 = fmaxf(m_[1], rm1);
        float f0 = ex2f(m_[0] - mn0), f1 = ex2f(m_[1] - mn1);
        float rs0 = 0.f, rs1 = 0.f;
#pragma unroll
        for (int nt = 0; nt < 8; nt++) {
            float p00 = ex2f(sacc[nt][0] - mn0);
            float p01 = ex2f(sacc[nt][1] - mn0);
            float p10 = ex2f(sacc[nt][2] - mn1);
            float p11 = ex2f(sacc[nt][3] - mn1);
            rs0 += p00 + p01; rs1 += p10 + p11;
            Pw[gr*68 + nt*8 + tg*2]     = tf32_rna(p00);
            Pw[gr*68 + nt*8 + tg*2 + 1] = tf32_rna(p01);
            Pw[(gr+8)*68 + nt*8 + tg*2]     = tf32_rna(p10);
            Pw[(gr+8)*68 + nt*8 + tg*2 + 1] = tf32_rna(p11);
        }
        rs0 += __shfl_xor_sync(0xffffffffu, rs0, 1);
        rs0 += __shfl_xor_sync(0xffffffffu, rs0, 2);
        rs1 += __shfl_xor_sync(0xffffffffu, rs1, 1);
        rs1 += __shfl_xor_sync(0xffffffffu, rs1, 2);
        l_[0] = l_[0]*f0 + rs0;  l_[1] = l_[1]*f1 + rs1;
        m_[0] = mn0;             m_[1] = mn1;
#pragma unroll
        for (int nt = 0; nt < 16; nt++) {
            oacc[nt][0] *= f0; oacc[nt][1] *= f0;
            oacc[nt][2] *= f1; oacc[nt][3] *= f1;
        }
        __syncwarp();

        // ---- O += P V : 16 n-tiles (128 dims), k = 64 keys
#pragma unroll
        for (int kb = 0; kb < 8; kb++) {
            uint32_t ap[4];
            ap[0] = Pw[gr*68 + kb*8 + tg];
            ap[1] = Pw[(gr+8)*68 + kb*8 + tg];
            ap[2] = Pw[gr*68 + kb*8 + tg + 4];
            ap[3] = Pw[(gr+8)*68 + kb*8 + tg + 4];
#pragma unroll
            for (int nt = 0; nt < 16; nt++) {
                uint32_t b0 = Vs[(kb*8 + tg)*132 + nt*8 + gr];
                uint32_t b1 = Vs[(kb*8 + tg + 4)*132 + nt*8 + gr];
                MMA_TF32(oacc[nt], ap, b0, b1);
            }
        }
    }

    // ---- epilogue: O /= l
    const float inv0 = 1.0f / l_[0], inv1 = 1.0f / l_[1];
    float* Ob = O + ((size_t)(b*SEQ + q0 + m0))*QDIM + h*HD;
#pragma unroll
    for (int nt = 0; nt < 16; nt++) {
        float2 v0 = { oacc[nt][0]*inv0, oacc[nt][1]*inv0 };
        float2 v1 = { oacc[nt][2]*inv1, oacc[nt][3]*inv1 };
        *(float2*)(Ob + (size_t)gr*QDIM + nt*8 + tg*2)       = v0;
        *(float2*)(Ob + (size_t)(gr+8)*QDIM + nt*8 + tg*2)   = v1;
    }
}

// ---------------------------------------------------------------------------
extern "C" void kernel_launch(void* const* d_in, const int* in_sizes, int n_in,
                              void* d_out, int out_size)
{
    const float* x    = (const float*)d_in[0];
    const float* cosp = (const float*)d_in[1];
    const float* sinp = (const float*)d_in[2];
    const float* Wq   = (const float*)d_in[3];
    const float* bq   = (const float*)d_in[4];
    const float* Wkv  = (const float*)d_in[5];
    const float* bkv  = (const float*)d_in[6];
    const float* Wo   = (const float*)d_in[7];
    const float* bo   = (const float*)d_in[8];
    const int*   causal = (const int*)d_in[9];
    float* out = (float*)d_out;

    float *q, *kv, *vo, *wqt, *wkvt, *wot;
    cudaGetSymbolAddress((void**)&q,    g_q);
    cudaGetSymbolAddress((void**)&kv,   g_kv);
    cudaGetSymbolAddress((void**)&vo,   g_vo);
    cudaGetSymbolAddress((void**)&wqt,  g_wqt);
    cudaGetSymbolAddress((void**)&wkvt, g_wkvt);
    cudaGetSymbolAddress((void**)&wot,  g_wot);

    cudaFuncSetAttribute(flash_tf32,
                         cudaFuncAttributeMaxDynamicSharedMemorySize, FA_SMEM);

    // W transposes: [K,N] -> [N,K]
    transpose_kernel<<<dim3(QDIM/32,  DIM/32),  dim3(32,8)>>>(Wq,  wqt,  DIM,  QDIM);
    transpose_kernel<<<dim3(KVDIM/32, DIM/32),  dim3(32,8)>>>(Wkv, wkvt, DIM,  KVDIM);
    transpose_kernel<<<dim3(DIM/32,   QDIM/32), dim3(32,8)>>>(Wo,  wot,  QDIM, DIM);

    gemm_tf32<<<dim3(QDIM/128,  ROWS/128), 256>>>(x, wqt,  bq,  q,  ROWS, QDIM,  DIM);
    gemm_tf32<<<dim3(KVDIM/128, ROWS/128), 256>>>(x, wkvt, bkv, kv, ROWS, KVDIM, DIM);

    rope_kernel<<<ROWS, 256>>>(q, kv, cosp, sinp);

    flash_tf32<<<dim3(SEQ/128, NH, BATCH), 256, FA_SMEM>>>(q, kv, vo, causal);

    gemm_tf32<<<dim3(DIM/128, ROWS/128), 256>>>(vo, wot, bo, out, ROWS, DIM, DIM);
}